// round 11
// baseline (speedup 1.0000x reference)
#include <cuda_runtime.h>
#include <cuda_fp16.h>
#include <math.h>
#include <stdint.h>

#define N_TOK 8192
#define DIM   1024
#define NEXP  8
#define DFF   4096
#define NPAIR (2 * N_TOK)

// ======================= device scratch (statics only) =======================
__device__ __half g_X[(size_t)N_TOK * DIM];            // x fp16
__device__ __half g_W1t[(size_t)NEXP * DFF * DIM];     // [e][n][k] fp16
__device__ __half g_W2t[(size_t)NEXP * DIM * DFF];     // [e][d][f] fp16
__device__ __half g_H[(size_t)NPAIR * DFF];            // silu(h) fp16
__device__ float g_O[(size_t)NPAIR * DIM];
__device__ int   g_count[NEXP], g_offset[NEXP], g_cursor[NEXP];
__device__ int   g_pair_token[NPAIR];
__device__ float g_pair_weight[NPAIR];
__device__ int   g_tok2pair[NPAIR];
__device__ int   g_tok_e[NPAIR];
__device__ float g_tok_w[NPAIR];

// ======================= PTX helpers =======================
__device__ __forceinline__ uint32_t smem_u32(const void* p) {
    uint32_t a;
    asm("{ .reg .u64 t; cvta.to.shared.u64 t, %1; cvt.u32.u64 %0, t; }"
        : "=r"(a) : "l"(p));
    return a;
}
__device__ __forceinline__ void cp16(uint32_t dst, const void* src, bool valid) {
    int sz = valid ? 16 : 0;
    asm volatile("cp.async.cg.shared.global [%0], [%1], 16, %2;"
                 :: "r"(dst), "l"(src), "r"(sz));
}
#define CP_COMMIT() asm volatile("cp.async.commit_group;" ::: "memory")
#define CP_WAIT(n)  asm volatile("cp.async.wait_group %0;" :: "n"(n) : "memory")

__device__ __forceinline__ void ldsm_x4(uint32_t* r, uint32_t addr) {
    asm volatile("ldmatrix.sync.aligned.m8n8.x4.shared.b16 {%0,%1,%2,%3}, [%4];"
                 : "=r"(r[0]), "=r"(r[1]), "=r"(r[2]), "=r"(r[3]) : "r"(addr));
}
// fp16-accumulator MMA: D(f16) = A(f16)*B(f16) + C(f16)
__device__ __forceinline__ void mma_f16acc(uint32_t* c2, const uint32_t* a,
                                           uint32_t b0, uint32_t b1) {
    asm volatile("mma.sync.aligned.m16n8k16.row.col.f16.f16.f16.f16 "
                 "{%0,%1},{%2,%3,%4,%5},{%6,%7},{%0,%1};"
                 : "+r"(c2[0]), "+r"(c2[1])
                 : "r"(a[0]), "r"(a[1]), "r"(a[2]), "r"(a[3]), "r"(b0), "r"(b1));
}

// ======================= merged weight convert + init =======================
__global__ void k_convert_all(const float* __restrict__ w1,
                              const float* __restrict__ w2) {
    __shared__ float tile[32][33];
    int z = blockIdx.z;
    int which = z >> 3;
    int e = z & 7;
    int bid = blockIdx.y * gridDim.x + blockIdx.x;   // 0..4095
    int tid = threadIdx.x;

    if (z == 0 && bid == 0 && tid < NEXP) { g_count[tid] = 0; g_cursor[tid] = 0; }

    const float* W;
    __half* T;
    int K, Ncols, n0, k0;
    if (which == 0) {            // W1: [e][K=1024][N=4096] -> [e][n][k]
        K = DIM; Ncols = DFF;
        n0 = (bid & 127) * 32;
        k0 = (bid >> 7) * 32;
        W = w1; T = &g_W1t[0];
    } else {                     // W2: [e][K=4096][N=1024] -> [e][d][f]
        K = DFF; Ncols = DIM;
        n0 = (bid & 31) * 32;
        k0 = (bid >> 5) * 32;
        W = w2; T = &g_W2t[0];
    }
    const float* We = W + (size_t)e * K * Ncols;
    {
        int tx = tid & 31, ty = tid >> 5;
#pragma unroll
        for (int j = 0; j < 4; j++)
            tile[ty + 8 * j][tx] = We[(size_t)(k0 + ty + 8 * j) * Ncols + n0 + tx];
    }
    __syncthreads();
    size_t obase = (size_t)e * Ncols * K;
    {
        int kp = tid & 15;
        int nb = tid >> 4;
#pragma unroll
        for (int jn = 0; jn < 2; jn++) {
            int n = nb + 16 * jn;
            __half2 h = __floats2half2_rn(tile[kp * 2][n], tile[kp * 2 + 1][n]);
            *(__half2*)&T[obase + (size_t)(n0 + n) * K + k0 + kp * 2] = h;
        }
    }
}

// ======================= router + fused x -> fp16 =======================
__global__ void k_router(const float* __restrict__ x, const float* __restrict__ gw) {
    int warp = (blockIdx.x * blockDim.x + threadIdx.x) >> 5;
    int lane = threadIdx.x & 31;
    if (warp >= N_TOK) return;
    const float* xr = x + (size_t)warp * DIM;
    __half* xo = &g_X[(size_t)warp * DIM];
    float acc[NEXP];
#pragma unroll
    for (int e = 0; e < NEXP; e++) acc[e] = 0.f;
    for (int d = lane * 2; d < DIM; d += 64) {
        float2 xv = *(const float2*)(xr + d);
        *(__half2*)(xo + d) = __floats2half2_rn(xv.x, xv.y);
        const float4* g4a = (const float4*)(gw + (size_t)d * NEXP);
        const float4* g4b = (const float4*)(gw + (size_t)(d + 1) * NEXP);
        float4 a = g4a[0], b = g4a[1];
        acc[0] += xv.x * a.x; acc[1] += xv.x * a.y; acc[2] += xv.x * a.z; acc[3] += xv.x * a.w;
        acc[4] += xv.x * b.x; acc[5] += xv.x * b.y; acc[6] += xv.x * b.z; acc[7] += xv.x * b.w;
        a = g4b[0]; b = g4b[1];
        acc[0] += xv.y * a.x; acc[1] += xv.y * a.y; acc[2] += xv.y * a.z; acc[3] += xv.y * a.w;
        acc[4] += xv.y * b.x; acc[5] += xv.y * b.y; acc[6] += xv.y * b.z; acc[7] += xv.y * b.w;
    }
#pragma unroll
    for (int e = 0; e < NEXP; e++)
#pragma unroll
        for (int s = 16; s > 0; s >>= 1)
            acc[e] += __shfl_xor_sync(0xFFFFFFFFu, acc[e], s);
    if (lane == 0) {
        int e0 = 0; float b0 = acc[0];
#pragma unroll
        for (int e = 1; e < NEXP; e++) if (acc[e] > b0) { b0 = acc[e]; e0 = e; }
        int e1 = -1; float b1 = -INFINITY;
#pragma unroll
        for (int e = 0; e < NEXP; e++) if (e != e0 && acc[e] > b1) { b1 = acc[e]; e1 = e; }
        float w0 = 1.f / (1.f + expf(b1 - b0));
        g_tok_e[2 * warp] = e0;      g_tok_e[2 * warp + 1] = e1;
        g_tok_w[2 * warp] = w0;      g_tok_w[2 * warp + 1] = 1.f - w0;
        atomicAdd(&g_count[e0], 1);
        atomicAdd(&g_count[e1], 1);
    }
}

// ======================= assign (with in-block prefix) ========
__global__ void k_assign() {
    __shared__ int s_off[NEXP];
    if (threadIdx.x < NEXP) {
        int s = 0;
        for (int e = 0; e < threadIdx.x; e++) s += g_count[e];
        s_off[threadIdx.x] = s;
        if (blockIdx.x == 0) g_offset[threadIdx.x] = s;
    }
    __syncthreads();
    int t = blockIdx.x * blockDim.x + threadIdx.x;
    if (t >= N_TOK) return;
#pragma unroll
    for (int s = 0; s < 2; s++) {
        int e = g_tok_e[2 * t + s];
        int pos = s_off[e] + atomicAdd(&g_cursor[e], 1);
        g_pair_token[pos]  = t;
        g_pair_weight[pos] = g_tok_w[2 * t + s];
        g_tok2pair[2 * t + s] = pos;
    }
}

// ======================= mma.sync GEMM =======================
#define PLANE_B (128 * 128)             // 16384
#define STAGE_B (2 * PLANE_B)           // 32768
#define SMEM_BYTES (2 * STAGE_B)        // 65536 -> 2 CTAs/SM

static __device__ __forceinline__ uint32_t swz(uint32_t off) {
    return off ^ ((off >> 3) & 0x70);
}

// G1: H = silu(X_gathered @ W1t^T)   K=1024 (NC=16)
// !G1: O = w * (H @ W2t^T)           K=4096 (NC=64)
template <int NC, bool G1>
__global__ __launch_bounds__(256, 2) void k_mma() {
    const int e    = blockIdx.z;
    const int cnt  = g_count[e];
    const int row0 = blockIdx.y * 128;
    if (row0 >= cnt) return;
    const int off  = g_offset[e];
    const int n0   = blockIdx.x * 128;

    extern __shared__ char dynsmem[];
    const uint32_t sb = smem_u32(dynsmem);

    const int tid  = threadIdx.x;
    const int lane = tid & 31;
    const int wid  = tid >> 5;
    const int wm   = wid & 1;      // 0..1 (64 rows each)
    const int wn   = wid >> 1;     // 0..3 (32 cols each)

    // ---- global load: thread loads row r = tid>>1, half = tid&1 (64B) ----
    const int r    = tid >> 1;
    const int half = tid & 1;
    const int row  = row0 + r;
    const bool vA  = row < cnt;

    const char* srcA;
    const char* srcB;
    if (G1) {
        int tok = vA ? g_pair_token[off + row] : 0;
        srcA = (const char*)(&g_X[0] + (size_t)tok * DIM) + half * 64;
        srcB = (const char*)(&g_W1t[0] + ((size_t)e * DFF + n0 + r) * DIM) + half * 64;
    } else {
        size_t p = (size_t)(vA ? off + row : 0);
        srcA = (const char*)(&g_H[0] + p * DFF) + half * 64;
        srcB = (const char*)(&g_W2t[0] + ((size_t)e * DIM + n0 + r) * DFF) + half * 64;
    }

    // ---- ldmatrix addressing: XOR mask reduces to lrow<<4 ----
    const int mat  = lane >> 3;
    const int lrow = lane & 7;
    const uint32_t xmask = (uint32_t)(lrow << 4);
    const uint32_t aBase = (uint32_t)((wm * 64 + (mat & 1) * 8 + lrow) * 128 + (mat >> 1) * 16);
    const uint32_t bBase = (uint32_t)((wn * 32 + (mat >> 1) * 8 + lrow) * 128 + (mat & 1) * 16);

    float c[4][4][4];   // fp32 master accumulators
#pragma unroll
    for (int i = 0; i < 4; i++)
#pragma unroll
        for (int j = 0; j < 4; j++)
#pragma unroll
            for (int q = 0; q < 4; q++) c[i][j][q] = 0.f;

    auto load_stage = [&](int cidx) {
        uint32_t st = sb + (uint32_t)(cidx & 1) * STAGE_B;
        size_t ko = (size_t)cidx * 128;
#pragma unroll
        for (int j = 0; j < 4; j++) {
            uint32_t d = swz((uint32_t)(r * 128 + half * 64 + j * 16));
            cp16(st + d, srcA + ko + j * 16, vA);
            cp16(st + PLANE_B + d, srcB + ko + j * 16, true);
        }
        CP_COMMIT();
    };

    load_stage(0);

    for (int cidx = 0; cidx < NC; cidx++) {
        CP_WAIT(0);
        __syncthreads();
        if (cidx + 1 < NC) load_stage(cidx + 1);

        uint32_t st = sb + (uint32_t)(cidx & 1) * STAGE_B;

        // fp16 chunk accumulators (chain of 4 MMAs, then spill to fp32)
        uint32_t hc[4][4][2];
#pragma unroll
        for (int tm = 0; tm < 4; tm++)
#pragma unroll
            for (int tn = 0; tn < 4; tn++) { hc[tm][tn][0] = 0u; hc[tm][tn][1] = 0u; }

#pragma unroll
        for (int ks = 0; ks < 4; ks++) {
            uint32_t kso = (uint32_t)(ks * 32);
            uint32_t a[4][4], b[2][4];
#pragma unroll
            for (int tm = 0; tm < 4; tm++)
                ldsm_x4(a[tm], st + ((aBase + (uint32_t)(tm * 16 * 128) + kso) ^ xmask));
#pragma unroll
            for (int tp = 0; tp < 2; tp++)
                ldsm_x4(b[tp], st + PLANE_B + ((bBase + (uint32_t)(tp * 16 * 128) + kso) ^ xmask));
#pragma unroll
            for (int tm = 0; tm < 4; tm++)
#pragma unroll
                for (int tp = 0; tp < 2; tp++) {
                    mma_f16acc(hc[tm][tp * 2 + 0], a[tm], b[tp][0], b[tp][1]);
                    mma_f16acc(hc[tm][tp * 2 + 1], a[tm], b[tp][2], b[tp][3]);
                }
        }

        // spill chunk fp16 accumulators into fp32 masters
#pragma unroll
        for (int tm = 0; tm < 4; tm++)
#pragma unroll
            for (int tn = 0; tn < 4; tn++) {
                __half2 h0 = *reinterpret_cast<__half2*>(&hc[tm][tn][0]);
                float2 f0 = __half22float2(h0);
                c[tm][tn][0] += f0.x;
                c[tm][tn][1] += f0.y;
                __half2 h1 = *reinterpret_cast<__half2*>(&hc[tm][tn][1]);
                float2 f1 = __half22float2(h1);
                c[tm][tn][2] += f1.x;
                c[tm][tn][3] += f1.y;
            }
    }

    // ---- epilogue ----
    const int g   = lane >> 2;
    const int tig = lane & 3;
#pragma unroll
    for (int tm = 0; tm < 4; tm++) {
#pragma unroll
        for (int half_m = 0; half_m < 2; half_m++) {
            int rr = row0 + wm * 64 + tm * 16 + g + half_m * 8;
            if (rr >= cnt) continue;
            if (G1) {
                size_t hrow = (size_t)(off + rr) * DFF + n0 + wn * 32 + tig * 2;
#pragma unroll
                for (int tn = 0; tn < 4; tn++) {
                    float v0 = c[tm][tn][half_m * 2 + 0];
                    float v1 = c[tm][tn][half_m * 2 + 1];
                    v0 = v0 / (1.f + __expf(-v0));
                    v1 = v1 / (1.f + __expf(-v1));
                    *(__half2*)(&g_H[0] + hrow + tn * 8) = __floats2half2_rn(v0, v1);
                }
            } else {
                float wgt = g_pair_weight[off + rr];
                size_t orow = (size_t)(off + rr) * DIM + n0 + wn * 32 + tig * 2;
#pragma unroll
                for (int tn = 0; tn < 4; tn++) {
                    float2 o;
                    o.x = wgt * c[tm][tn][half_m * 2 + 0];
                    o.y = wgt * c[tm][tn][half_m * 2 + 1];
                    *(float2*)(g_O + orow + tn * 8) = o;
                }
            }
        }
    }
}

// ======================= combine =======================
__global__ void k_combine(float* __restrict__ y) {
    int i = blockIdx.x * blockDim.x + threadIdx.x;
    const int V = DIM / 4;
    if (i >= N_TOK * V) return;
    int tok = i / V;
    int c   = i - tok * V;
    int p0 = g_tok2pair[2 * tok];
    int p1 = g_tok2pair[2 * tok + 1];
    float4 a = ((const float4*)(g_O + (size_t)p0 * DIM))[c];
    float4 b = ((const float4*)(g_O + (size_t)p1 * DIM))[c];
    float4 r;
    r.x = a.x + b.x; r.y = a.y + b.y; r.z = a.z + b.z; r.w = a.w + b.w;
    ((float4*)y)[i] = r;
}

// ======================= launch =======================
extern "C" void kernel_launch(void* const* d_in, const int* in_sizes, int n_in,
                              void* d_out, int out_size) {
    const float* x  = (const float*)d_in[0];   // [N, D]
    const float* gw = (const float*)d_in[1];   // [D, E]
    const float* w1 = (const float*)d_in[2];   // [E, D, DFF]
    const float* w2 = (const float*)d_in[3];   // [E, DFF, D]
    float* y = (float*)d_out;

    cudaFuncSetAttribute((const void*)k_mma<DIM / 64, true>,
                         cudaFuncAttributeMaxDynamicSharedMemorySize, SMEM_BYTES);
    cudaFuncSetAttribute((const void*)k_mma<DFF / 64, false>,
                         cudaFuncAttributeMaxDynamicSharedMemorySize, SMEM_BYTES);

    // #1: merged weight converts (+ counter init)
    k_convert_all<<<dim3(128, 32, 2 * NEXP), 256>>>(w1, w2);
    // #2: router (+ fused x convert)
    k_router<<<N_TOK / 8, 256>>>(x, gw);
    // #3: assign (with in-block prefix)
    k_assign<<<(N_TOK + 255) / 256, 256>>>();
    // #4: GEMM1  <-- ncu capture slot
    k_mma<DIM / 64, true><<<dim3(DFF / 128, NPAIR / 128, NEXP), 256, SMEM_BYTES>>>();
    // #5: GEMM2
    k_mma<DFF / 64, false><<<dim3(DIM / 128, NPAIR / 128, NEXP), 256, SMEM_BYTES>>>();
    // #6: combine
    k_combine<<<(N_TOK * DIM / 4 + 255) / 256, 256>>>(y);
}

// round 12
// speedup vs baseline: 1.2166x; 1.2166x over previous
#include <cuda_runtime.h>
#include <cuda_fp16.h>
#include <math.h>
#include <stdint.h>

#define N_TOK 8192
#define DIM   1024
#define NEXP  8
#define DFF   4096
#define NPAIR (2 * N_TOK)

// ======================= device scratch (statics only) =======================
__device__ __half g_X[(size_t)N_TOK * DIM];            // x fp16
__device__ __half g_W1t[(size_t)NEXP * DFF * DIM];     // [e][n][k] fp16
__device__ __half g_W2t[(size_t)NEXP * DIM * DFF];     // [e][d][f] fp16
__device__ __half g_H[(size_t)NPAIR * DFF];            // silu(h) fp16
__device__ __half g_O[(size_t)NPAIR * DIM];            // weighted expert outs fp16
__device__ int   g_count[NEXP], g_offset[NEXP], g_cursor[NEXP];
__device__ int   g_pair_token[NPAIR];
__device__ float g_pair_weight[NPAIR];
__device__ int   g_tok2pair[NPAIR];
__device__ int   g_tok_e[NPAIR];
__device__ float g_tok_w[NPAIR];

// ======================= PTX helpers =======================
__device__ __forceinline__ uint32_t smem_u32(const void* p) {
    uint32_t a;
    asm("{ .reg .u64 t; cvta.to.shared.u64 t, %1; cvt.u32.u64 %0, t; }"
        : "=r"(a) : "l"(p));
    return a;
}
__device__ __forceinline__ void cp16(uint32_t dst, const void* src, bool valid) {
    int sz = valid ? 16 : 0;
    asm volatile("cp.async.cg.shared.global [%0], [%1], 16, %2;"
                 :: "r"(dst), "l"(src), "r"(sz));
}
#define CP_COMMIT() asm volatile("cp.async.commit_group;" ::: "memory")
#define CP_WAIT(n)  asm volatile("cp.async.wait_group %0;" :: "n"(n) : "memory")

__device__ __forceinline__ void ldsm_x4(uint32_t* r, uint32_t addr) {
    asm volatile("ldmatrix.sync.aligned.m8n8.x4.shared.b16 {%0,%1,%2,%3}, [%4];"
                 : "=r"(r[0]), "=r"(r[1]), "=r"(r[2]), "=r"(r[3]) : "r"(addr));
}
__device__ __forceinline__ void mma_fp16(float* c, const uint32_t* a,
                                         uint32_t b0, uint32_t b1) {
    asm volatile("mma.sync.aligned.m16n8k16.row.col.f32.f16.f16.f32 "
                 "{%0,%1,%2,%3},{%4,%5,%6,%7},{%8,%9},{%0,%1,%2,%3};"
                 : "+f"(c[0]), "+f"(c[1]), "+f"(c[2]), "+f"(c[3])
                 : "r"(a[0]), "r"(a[1]), "r"(a[2]), "r"(a[3]), "r"(b0), "r"(b1));
}

// ======================= weight convert (64x64 tiles, coalesced) + init ======
// grid (64, 16, 16): z -> which/expert; bid = y*64+x in [0,1024)
__global__ __launch_bounds__(256) void k_convert_all(const float* __restrict__ w1,
                                                     const float* __restrict__ w2) {
    __shared__ float tile[64][65];    // [n][k], transposed at load
    int z = blockIdx.z;
    int which = z >> 3;
    int e = z & 7;
    int bid = blockIdx.y * gridDim.x + blockIdx.x;
    int tid = threadIdx.x;

    if (z == 0 && bid == 0 && tid < NEXP) { g_count[tid] = 0; g_cursor[tid] = 0; }

    const float* W;
    __half* T;
    int K, Ncols, n0, k0;
    if (which == 0) {            // W1: [e][K=1024][N=4096] -> [e][n][k]
        K = DIM; Ncols = DFF;
        n0 = (bid & 63) * 64;    // 64 n-tiles
        k0 = (bid >> 6) * 64;    // 16 k-tiles
        W = w1; T = &g_W1t[0];
    } else {                     // W2: [e][K=4096][N=1024] -> [e][d][f]
        K = DFF; Ncols = DIM;
        n0 = (bid & 15) * 64;    // 16 n-tiles
        k0 = (bid >> 4) * 64;    // 64 k-tiles
        W = w2; T = &g_W2t[0];
    }
    const float* We = W + (size_t)e * K * Ncols;

    int tx = tid & 63, ty = tid >> 6;   // tx = n-col, ty = k-row group
#pragma unroll
    for (int j = 0; j < 16; j++) {
        int kr = j * 4 + ty;
        tile[tx][kr] = We[(size_t)(k0 + kr) * Ncols + n0 + tx];   // 256B coalesced
    }
    __syncthreads();

    size_t obase = (size_t)e * Ncols * K;
    int w = tid >> 5, lane = tid & 31;
#pragma unroll
    for (int i = 0; i < 8; i++) {
        int n = w * 8 + i;
        __half2 h = __floats2half2_rn(tile[n][lane * 2], tile[n][lane * 2 + 1]);
        *(__half2*)&T[obase + (size_t)(n0 + n) * K + k0 + lane * 2] = h;  // 128B/warp
    }
}

// ======================= router: 4 tokens/warp + fused x->fp16 ===============
__global__ void k_router(const float* __restrict__ x, const float* __restrict__ gw) {
    int warp = (blockIdx.x * blockDim.x + threadIdx.x) >> 5;
    int lane = threadIdx.x & 31;
    if (warp >= N_TOK / 4) return;
    int t0 = warp * 4;
    const float* xb = x + (size_t)t0 * DIM;
    __half* xo = &g_X[(size_t)t0 * DIM];

    float acc[4][8];
#pragma unroll
    for (int t = 0; t < 4; t++)
#pragma unroll
        for (int e = 0; e < 8; e++) acc[t][e] = 0.f;

    for (int d = lane; d < DIM; d += 32) {
        float4 ga = *(const float4*)(gw + (size_t)d * NEXP);
        float4 gb = *(const float4*)(gw + (size_t)d * NEXP + 4);
#pragma unroll
        for (int t = 0; t < 4; t++) {
            float xv = xb[t * DIM + d];
            xo[t * DIM + d] = __float2half(xv);
            acc[t][0] += xv * ga.x; acc[t][1] += xv * ga.y;
            acc[t][2] += xv * ga.z; acc[t][3] += xv * ga.w;
            acc[t][4] += xv * gb.x; acc[t][5] += xv * gb.y;
            acc[t][6] += xv * gb.z; acc[t][7] += xv * gb.w;
        }
    }
#pragma unroll
    for (int t = 0; t < 4; t++)
#pragma unroll
        for (int e = 0; e < 8; e++)
#pragma unroll
            for (int s = 16; s > 0; s >>= 1)
                acc[t][e] += __shfl_xor_sync(0xFFFFFFFFu, acc[t][e], s);

    if (lane < 4) {
        int t = t0 + lane;
        float* a = acc[lane];
        int e0 = 0; float b0 = a[0];
#pragma unroll
        for (int e = 1; e < NEXP; e++) if (a[e] > b0) { b0 = a[e]; e0 = e; }
        int e1 = -1; float b1 = -INFINITY;
#pragma unroll
        for (int e = 0; e < NEXP; e++) if (e != e0 && a[e] > b1) { b1 = a[e]; e1 = e; }
        float w0 = 1.f / (1.f + expf(b1 - b0));
        g_tok_e[2 * t] = e0;      g_tok_e[2 * t + 1] = e1;
        g_tok_w[2 * t] = w0;      g_tok_w[2 * t + 1] = 1.f - w0;
        atomicAdd(&g_count[e0], 1);
        atomicAdd(&g_count[e1], 1);
    }
}

// ======================= assign (with in-block prefix) ========
__global__ void k_assign() {
    __shared__ int s_off[NEXP];
    if (threadIdx.x < NEXP) {
        int s = 0;
        for (int e = 0; e < threadIdx.x; e++) s += g_count[e];
        s_off[threadIdx.x] = s;
        if (blockIdx.x == 0) g_offset[threadIdx.x] = s;
    }
    __syncthreads();
    int t = blockIdx.x * blockDim.x + threadIdx.x;
    if (t >= N_TOK) return;
#pragma unroll
    for (int s = 0; s < 2; s++) {
        int e = g_tok_e[2 * t + s];
        int pos = s_off[e] + atomicAdd(&g_cursor[e], 1);
        g_pair_token[pos]  = t;
        g_pair_weight[pos] = g_tok_w[2 * t + s];
        g_tok2pair[2 * t + s] = pos;
    }
}

// ======================= mma.sync GEMM =======================
#define PLANE_B (128 * 128)             // 16384
#define STAGE_B (2 * PLANE_B)           // 32768
#define SMEM_BYTES (2 * STAGE_B)        // 65536 -> 2 CTAs/SM

static __device__ __forceinline__ uint32_t swz(uint32_t off) {
    return off ^ ((off >> 3) & 0x70);
}

// G1: H = silu(X_gathered @ W1t^T)   K=1024 (NC=16)
// !G1: O(fp16) = w * (H @ W2t^T)     K=4096 (NC=64)
template <int NC, bool G1>
__global__ __launch_bounds__(256, 2) void k_mma() {
    const int e    = blockIdx.z;
    const int cnt  = g_count[e];
    const int row0 = blockIdx.y * 128;
    if (row0 >= cnt) return;
    const int off  = g_offset[e];
    const int n0   = blockIdx.x * 128;

    extern __shared__ char dynsmem[];
    const uint32_t sb = smem_u32(dynsmem);

    const int tid  = threadIdx.x;
    const int lane = tid & 31;
    const int wid  = tid >> 5;
    const int wm   = wid & 1;      // 0..1 (64 rows each)
    const int wn   = wid >> 1;     // 0..3 (32 cols each)

    const int r    = tid >> 1;
    const int half = tid & 1;
    const int row  = row0 + r;
    const bool vA  = row < cnt;

    const char* srcA;
    const char* srcB;
    if (G1) {
        int tok = vA ? g_pair_token[off + row] : 0;
        srcA = (const char*)(&g_X[0] + (size_t)tok * DIM) + half * 64;
        srcB = (const char*)(&g_W1t[0] + ((size_t)e * DFF + n0 + r) * DIM) + half * 64;
    } else {
        size_t p = (size_t)(vA ? off + row : 0);
        srcA = (const char*)(&g_H[0] + p * DFF) + half * 64;
        srcB = (const char*)(&g_W2t[0] + ((size_t)e * DIM + n0 + r) * DFF) + half * 64;
    }
    uint32_t dstO[4];
#pragma unroll
    for (int j = 0; j < 4; j++)
        dstO[j] = swz((uint32_t)(r * 128 + half * 64 + j * 16));

    const int mat  = lane >> 3;
    const int lrow = lane & 7;
    const uint32_t xmask = (uint32_t)(lrow << 4);
    const uint32_t aBase = (uint32_t)((wm * 64 + (mat & 1) * 8 + lrow) * 128 + (mat >> 1) * 16);
    const uint32_t bBase = (uint32_t)((wn * 32 + (mat >> 1) * 8 + lrow) * 128 + (mat & 1) * 16);

    float c[4][4][4];
#pragma unroll
    for (int i = 0; i < 4; i++)
#pragma unroll
        for (int j = 0; j < 4; j++)
#pragma unroll
            for (int q = 0; q < 4; q++) c[i][j][q] = 0.f;

    auto load_stage = [&](int cidx) {
        uint32_t st = sb + (uint32_t)(cidx & 1) * STAGE_B;
        size_t ko = (size_t)cidx * 128;
#pragma unroll
        for (int j = 0; j < 4; j++)
            cp16(st + dstO[j], srcA + ko + j * 16, vA);
#pragma unroll
        for (int j = 0; j < 4; j++)
            cp16(st + PLANE_B + dstO[j], srcB + ko + j * 16, true);
        CP_COMMIT();
    };

    load_stage(0);

    for (int cidx = 0; cidx < NC; cidx++) {
        CP_WAIT(0);
        __syncthreads();
        if (cidx + 1 < NC) load_stage(cidx + 1);

        uint32_t st = sb + (uint32_t)(cidx & 1) * STAGE_B;
#pragma unroll
        for (int ks = 0; ks < 4; ks++) {
            uint32_t kso = (uint32_t)(ks * 32);
            uint32_t a[4][4], b[2][4];
#pragma unroll
            for (int tm = 0; tm < 4; tm++)
                ldsm_x4(a[tm], st + ((aBase + (uint32_t)(tm * 16 * 128) + kso) ^ xmask));
#pragma unroll
            for (int tp = 0; tp < 2; tp++)
                ldsm_x4(b[tp], st + PLANE_B + ((bBase + (uint32_t)(tp * 16 * 128) + kso) ^ xmask));
#pragma unroll
            for (int tm = 0; tm < 4; tm++)
#pragma unroll
                for (int tp = 0; tp < 2; tp++) {
                    mma_fp16(c[tm][tp * 2 + 0], a[tm], b[tp][0], b[tp][1]);
                    mma_fp16(c[tm][tp * 2 + 1], a[tm], b[tp][2], b[tp][3]);
                }
        }
    }

    // ---- epilogue ----
    const int g   = lane >> 2;
    const int tig = lane & 3;
#pragma unroll
    for (int tm = 0; tm < 4; tm++) {
#pragma unroll
        for (int half_m = 0; half_m < 2; half_m++) {
            int rr = row0 + wm * 64 + tm * 16 + g + half_m * 8;
            if (rr >= cnt) continue;
            if (G1) {
                size_t hrow = (size_t)(off + rr) * DFF + n0 + wn * 32 + tig * 2;
#pragma unroll
                for (int tn = 0; tn < 4; tn++) {
                    float v0 = c[tm][tn][half_m * 2 + 0];
                    float v1 = c[tm][tn][half_m * 2 + 1];
                    v0 = v0 / (1.f + __expf(-v0));
                    v1 = v1 / (1.f + __expf(-v1));
                    *(__half2*)(&g_H[0] + hrow + tn * 8) = __floats2half2_rn(v0, v1);
                }
            } else {
                float wgt = g_pair_weight[off + rr];
                size_t orow = (size_t)(off + rr) * DIM + n0 + wn * 32 + tig * 2;
#pragma unroll
                for (int tn = 0; tn < 4; tn++) {
                    *(__half2*)(&g_O[0] + orow + tn * 8) =
                        __floats2half2_rn(wgt * c[tm][tn][half_m * 2 + 0],
                                          wgt * c[tm][tn][half_m * 2 + 1]);
                }
            }
        }
    }
}

// ======================= combine (fp16 O -> fp32 y) =======================
__global__ void k_combine(float* __restrict__ y) {
    int i = blockIdx.x * blockDim.x + threadIdx.x;   // over float4s of y
    const int V = DIM / 4;
    if (i >= N_TOK * V) return;
    int tok = i / V;
    int c   = i - tok * V;
    int p0 = g_tok2pair[2 * tok];
    int p1 = g_tok2pair[2 * tok + 1];
    const __half2* o0 = (const __half2*)(&g_O[0] + (size_t)p0 * DIM) + c * 2;
    const __half2* o1 = (const __half2*)(&g_O[0] + (size_t)p1 * DIM) + c * 2;
    float2 a0 = __half22float2(o0[0]);
    float2 a1 = __half22float2(o0[1]);
    float2 b0 = __half22float2(o1[0]);
    float2 b1 = __half22float2(o1[1]);
    float4 r;
    r.x = a0.x + b0.x; r.y = a0.y + b0.y;
    r.z = a1.x + b1.x; r.w = a1.y + b1.y;
    ((float4*)y)[i] = r;
}

// ======================= launch =======================
extern "C" void kernel_launch(void* const* d_in, const int* in_sizes, int n_in,
                              void* d_out, int out_size) {
    const float* x  = (const float*)d_in[0];   // [N, D]
    const float* gw = (const float*)d_in[1];   // [D, E]
    const float* w1 = (const float*)d_in[2];   // [E, D, DFF]
    const float* w2 = (const float*)d_in[3];   // [E, DFF, D]
    float* y = (float*)d_out;

    cudaFuncSetAttribute((const void*)k_mma<DIM / 64, true>,
                         cudaFuncAttributeMaxDynamicSharedMemorySize, SMEM_BYTES);
    cudaFuncSetAttribute((const void*)k_mma<DFF / 64, false>,
                         cudaFuncAttributeMaxDynamicSharedMemorySize, SMEM_BYTES);

    // #1: merged weight converts (+ counter init)
    k_convert_all<<<dim3(64, 16, 2 * NEXP), 256>>>(w1, w2);
    // #2: router (4 tokens/warp, fused x convert)
    k_router<<<(N_TOK / 4) / 8, 256>>>(x, gw);
    // #3: assign
    k_assign<<<(N_TOK + 255) / 256, 256>>>();
    // #4: GEMM1  <-- ncu capture slot
    k_mma<DIM / 64, true><<<dim3(DFF / 128, NPAIR / 128, NEXP), 256, SMEM_BYTES>>>();
    // #5: GEMM2
    k_mma<DFF / 64, false><<<dim3(DIM / 128, NPAIR / 128, NEXP), 256, SMEM_BYTES>>>();
    // #6: combine
    k_combine<<<(N_TOK * DIM / 4 + 255) / 256, 256>>>(y);
}

// round 13
// speedup vs baseline: 1.2268x; 1.0084x over previous
#include <cuda_runtime.h>
#include <cuda_fp16.h>
#include <math.h>
#include <stdint.h>

#define N_TOK 8192
#define DIM   1024
#define NEXP  8
#define DFF   4096
#define NPAIR (2 * N_TOK)

// ======================= device scratch (statics only) =======================
__device__ __half g_X[(size_t)N_TOK * DIM];            // x fp16
__device__ __half g_W1t[(size_t)NEXP * DFF * DIM];     // [e][n][k] fp16
__device__ __half g_W2t[(size_t)NEXP * DIM * DFF];     // [e][d][f] fp16
__device__ __half g_H[(size_t)NPAIR * DFF];            // silu(h) fp16
__device__ __half g_O[(size_t)NPAIR * DIM];            // weighted expert outs fp16
__device__ int   g_count[NEXP], g_offset[NEXP], g_cursor[NEXP];
__device__ int   g_pair_token[NPAIR];
__device__ float g_pair_weight[NPAIR];
__device__ int   g_tok2pair[NPAIR];
__device__ int   g_tok_e[NPAIR];
__device__ float g_tok_w[NPAIR];

// ======================= PTX helpers =======================
__device__ __forceinline__ uint32_t smem_u32(const void* p) {
    uint32_t a;
    asm("{ .reg .u64 t; cvta.to.shared.u64 t, %1; cvt.u32.u64 %0, t; }"
        : "=r"(a) : "l"(p));
    return a;
}
__device__ __forceinline__ void cp16(uint32_t dst, const void* src, bool valid) {
    int sz = valid ? 16 : 0;
    asm volatile("cp.async.cg.shared.global [%0], [%1], 16, %2;"
                 :: "r"(dst), "l"(src), "r"(sz));
}
#define CP_COMMIT() asm volatile("cp.async.commit_group;" ::: "memory")
#define CP_WAIT(n)  asm volatile("cp.async.wait_group %0;" :: "n"(n) : "memory")

__device__ __forceinline__ void ldsm_x4(uint32_t* r, uint32_t addr) {
    asm volatile("ldmatrix.sync.aligned.m8n8.x4.shared.b16 {%0,%1,%2,%3}, [%4];"
                 : "=r"(r[0]), "=r"(r[1]), "=r"(r[2]), "=r"(r[3]) : "r"(addr));
}
__device__ __forceinline__ void mma_fp16(float* c, const uint32_t* a,
                                         uint32_t b0, uint32_t b1) {
    asm volatile("mma.sync.aligned.m16n8k16.row.col.f32.f16.f16.f32 "
                 "{%0,%1,%2,%3},{%4,%5,%6,%7},{%8,%9},{%0,%1,%2,%3};"
                 : "+f"(c[0]), "+f"(c[1]), "+f"(c[2]), "+f"(c[3])
                 : "r"(a[0]), "r"(a[1]), "r"(a[2]), "r"(a[3]), "r"(b0), "r"(b1));
}

static __device__ __forceinline__ uint32_t swz(uint32_t off) {
    return off ^ ((off >> 3) & 0x70);
}

// =========== device helper: transpose-convert one 64x64 fp32 tile ==========
// smem must provide >= 64*65*4 bytes. W row-major [K][Ncols]; T [n][k] fp16.
template <int NCOLS>
__device__ __forceinline__ void conv_tile(const float* __restrict__ We,
                                          __half* __restrict__ Te,
                                          float (*tile)[65],
                                          int n0, int k0, int K) {
    int tid = threadIdx.x;
    int tx = tid & 63, ty = tid >> 6;
#pragma unroll
    for (int j = 0; j < 16; j++) {
        int kr = j * 4 + ty;
        tile[tx][kr] = We[(size_t)(k0 + kr) * NCOLS + n0 + tx];
    }
    __syncthreads();
    int w = tid >> 5, lane = tid & 31;
#pragma unroll
    for (int i = 0; i < 8; i++) {
        int n = w * 8 + i;
        __half2 h = __floats2half2_rn(tile[n][lane * 2], tile[n][lane * 2 + 1]);
        *(__half2*)&Te[(size_t)(n0 + n) * K + k0 + lane * 2] = h;
    }
}

// ======== kernel 1: convert W1 (blocks [0,8192)) + router (blocks [8192,8448)) ========
__global__ __launch_bounds__(256) void k_conv1_router(const float* __restrict__ w1,
                                                      const float* __restrict__ x,
                                                      const float* __restrict__ gw) {
    __shared__ float tile[64][65];
    int bx = blockIdx.x;
    if (bx < 8192) {
        int e = bx >> 10, t = bx & 1023;
        int n0 = (t & 63) * 64, k0 = (t >> 6) * 64;   // Ncols=DFF(4096): 64 n-tiles, 16 k-tiles
        conv_tile<DFF>(w1 + (size_t)e * DIM * DFF,
                       &g_W1t[(size_t)e * DFF * DIM], tile, n0, k0, DIM);
        return;
    }
    // ---- router: 4 tokens/warp, fused x->fp16 ----
    int b = bx - 8192;
    int wid = threadIdx.x >> 5, lane = threadIdx.x & 31;
    int warp = b * 8 + wid;            // [0, 2048)
    int t0 = warp * 4;
    const float* xb = x + (size_t)t0 * DIM;
    __half* xo = &g_X[(size_t)t0 * DIM];

    float acc[4][8];
#pragma unroll
    for (int t = 0; t < 4; t++)
#pragma unroll
        for (int e = 0; e < 8; e++) acc[t][e] = 0.f;

    for (int d = lane; d < DIM; d += 32) {
        float4 ga = *(const float4*)(gw + (size_t)d * NEXP);
        float4 gb = *(const float4*)(gw + (size_t)d * NEXP + 4);
#pragma unroll
        for (int t = 0; t < 4; t++) {
            float xv = xb[t * DIM + d];
            xo[t * DIM + d] = __float2half(xv);
            acc[t][0] += xv * ga.x; acc[t][1] += xv * ga.y;
            acc[t][2] += xv * ga.z; acc[t][3] += xv * ga.w;
            acc[t][4] += xv * gb.x; acc[t][5] += xv * gb.y;
            acc[t][6] += xv * gb.z; acc[t][7] += xv * gb.w;
        }
    }
#pragma unroll
    for (int t = 0; t < 4; t++)
#pragma unroll
        for (int e = 0; e < 8; e++)
#pragma unroll
            for (int s = 16; s > 0; s >>= 1)
                acc[t][e] += __shfl_xor_sync(0xFFFFFFFFu, acc[t][e], s);

    if (lane < 4) {
        int t = t0 + lane;
        float* a = acc[lane];
        int e0 = 0; float b0 = a[0];
#pragma unroll
        for (int e = 1; e < NEXP; e++) if (a[e] > b0) { b0 = a[e]; e0 = e; }
        int e1 = -1; float b1 = -INFINITY;
#pragma unroll
        for (int e = 0; e < NEXP; e++) if (e != e0 && a[e] > b1) { b1 = a[e]; e1 = e; }
        float w0 = 1.f / (1.f + expf(b1 - b0));
        g_tok_e[2 * t] = e0;      g_tok_e[2 * t + 1] = e1;
        g_tok_w[2 * t] = w0;      g_tok_w[2 * t + 1] = 1.f - w0;
        atomicAdd(&g_count[e0], 1);
        atomicAdd(&g_count[e1], 1);
    }
}

// ======================= assign (with in-block prefix) ========
__global__ void k_assign() {
    __shared__ int s_off[NEXP];
    if (threadIdx.x < NEXP) {
        int s = 0;
        for (int e = 0; e < threadIdx.x; e++) s += g_count[e];
        s_off[threadIdx.x] = s;
        if (blockIdx.x == 0) g_offset[threadIdx.x] = s;
    }
    __syncthreads();
    int t = blockIdx.x * blockDim.x + threadIdx.x;
    if (t >= N_TOK) return;
#pragma unroll
    for (int s = 0; s < 2; s++) {
        int e = g_tok_e[2 * t + s];
        int pos = s_off[e] + atomicAdd(&g_cursor[e], 1);
        g_pair_token[pos]  = t;
        g_pair_weight[pos] = g_tok_w[2 * t + s];
        g_tok2pair[2 * t + s] = pos;
    }
}

// ======================= mma.sync GEMM cores =======================
#define PLANE_B (128 * 128)             // 16384
#define STAGE_B (2 * PLANE_B)           // 32768
#define SMEM_BYTES (2 * STAGE_B)        // 65536 -> 2 CTAs/SM

// Shared GEMM body. G1: H = silu(X_gathered @ W1t^T), K=1024 (NC=16)
//                  !G1: O(fp16) = w * (H @ W2t^T),    K=4096 (NC=64)
template <int NC, bool G1>
__device__ __forceinline__ void gemm_body(int e, char* dynsmem) {
    const int cnt  = g_count[e];
    const int row0 = blockIdx.y * 128;
    if (row0 >= cnt) return;
    const int off  = g_offset[e];
    const int n0   = blockIdx.x * 128;

    const uint32_t sb = smem_u32(dynsmem);
    const int tid  = threadIdx.x;
    const int lane = tid & 31;
    const int wid  = tid >> 5;
    const int wm   = wid & 1;
    const int wn   = wid >> 1;

    const int r    = tid >> 1;
    const int half = tid & 1;
    const int row  = row0 + r;
    const bool vA  = row < cnt;

    const char* srcA;
    const char* srcB;
    if (G1) {
        int tok = vA ? g_pair_token[off + row] : 0;
        srcA = (const char*)(&g_X[0] + (size_t)tok * DIM) + half * 64;
        srcB = (const char*)(&g_W1t[0] + ((size_t)e * DFF + n0 + r) * DIM) + half * 64;
    } else {
        size_t p = (size_t)(vA ? off + row : 0);
        srcA = (const char*)(&g_H[0] + p * DFF) + half * 64;
        srcB = (const char*)(&g_W2t[0] + ((size_t)e * DIM + n0 + r) * DFF) + half * 64;
    }
    uint32_t dstO[4];
#pragma unroll
    for (int j = 0; j < 4; j++)
        dstO[j] = swz((uint32_t)(r * 128 + half * 64 + j * 16));

    const int mat  = lane >> 3;
    const int lrow = lane & 7;
    const uint32_t xmask = (uint32_t)(lrow << 4);
    const uint32_t aBase = (uint32_t)((wm * 64 + (mat & 1) * 8 + lrow) * 128 + (mat >> 1) * 16);
    const uint32_t bBase = (uint32_t)((wn * 32 + (mat >> 1) * 8 + lrow) * 128 + (mat & 1) * 16);

    float c[4][4][4];
#pragma unroll
    for (int i = 0; i < 4; i++)
#pragma unroll
        for (int j = 0; j < 4; j++)
#pragma unroll
            for (int q = 0; q < 4; q++) c[i][j][q] = 0.f;

    auto load_stage = [&](int cidx) {
        uint32_t st = sb + (uint32_t)(cidx & 1) * STAGE_B;
        size_t ko = (size_t)cidx * 128;
#pragma unroll
        for (int j = 0; j < 4; j++)
            cp16(st + dstO[j], srcA + ko + j * 16, vA);
#pragma unroll
        for (int j = 0; j < 4; j++)
            cp16(st + PLANE_B + dstO[j], srcB + ko + j * 16, true);
        CP_COMMIT();
    };

    load_stage(0);

    for (int cidx = 0; cidx < NC; cidx++) {
        CP_WAIT(0);
        __syncthreads();
        if (cidx + 1 < NC) load_stage(cidx + 1);

        uint32_t st = sb + (uint32_t)(cidx & 1) * STAGE_B;
#pragma unroll
        for (int ks = 0; ks < 4; ks++) {
            uint32_t kso = (uint32_t)(ks * 32);
            uint32_t a[4][4], b[2][4];
#pragma unroll
            for (int tm = 0; tm < 4; tm++)
                ldsm_x4(a[tm], st + ((aBase + (uint32_t)(tm * 16 * 128) + kso) ^ xmask));
#pragma unroll
            for (int tp = 0; tp < 2; tp++)
                ldsm_x4(b[tp], st + PLANE_B + ((bBase + (uint32_t)(tp * 16 * 128) + kso) ^ xmask));
#pragma unroll
            for (int tm = 0; tm < 4; tm++)
#pragma unroll
                for (int tp = 0; tp < 2; tp++) {
                    mma_fp16(c[tm][tp * 2 + 0], a[tm], b[tp][0], b[tp][1]);
                    mma_fp16(c[tm][tp * 2 + 1], a[tm], b[tp][2], b[tp][3]);
                }
        }
    }

    const int g   = lane >> 2;
    const int tig = lane & 3;
#pragma unroll
    for (int tm = 0; tm < 4; tm++) {
#pragma unroll
        for (int half_m = 0; half_m < 2; half_m++) {
            int rr = row0 + wm * 64 + tm * 16 + g + half_m * 8;
            if (rr >= cnt) continue;
            if (G1) {
                size_t hrow = (size_t)(off + rr) * DFF + n0 + wn * 32 + tig * 2;
#pragma unroll
                for (int tn = 0; tn < 4; tn++) {
                    float v0 = c[tm][tn][half_m * 2 + 0];
                    float v1 = c[tm][tn][half_m * 2 + 1];
                    v0 = v0 / (1.f + __expf(-v0));
                    v1 = v1 / (1.f + __expf(-v1));
                    *(__half2*)(&g_H[0] + hrow + tn * 8) = __floats2half2_rn(v0, v1);
                }
            } else {
                float wgt = g_pair_weight[off + rr];
                size_t orow = (size_t)(off + rr) * DIM + n0 + wn * 32 + tig * 2;
#pragma unroll
                for (int tn = 0; tn < 4; tn++) {
                    *(__half2*)(&g_O[0] + orow + tn * 8) =
                        __floats2half2_rn(wgt * c[tm][tn][half_m * 2 + 0],
                                          wgt * c[tm][tn][half_m * 2 + 1]);
                }
            }
        }
    }
}

// ======== kernel 3: GEMM1 (z in [0,8)) + convert W2 (z in [8,10)) ========
__global__ __launch_bounds__(256, 2) void k_gemm1_conv2(const float* __restrict__ w2) {
    extern __shared__ char dynsmem[];
    int z = blockIdx.z;
    if (z < NEXP) {
        gemm_body<DIM / 64, true>(z, dynsmem);
        return;
    }
    // convert W2: idx in [0, 8192)
    int idx = (z - NEXP) * 4096 + blockIdx.y * 32 + blockIdx.x;
    int e = idx >> 10, t = idx & 1023;
    int n0 = (t & 15) * 64, k0 = (t >> 4) * 64;    // Ncols=DIM(1024): 16 n-tiles, 64 k-tiles
    float (*tile)[65] = (float(*)[65])dynsmem;
    conv_tile<DIM>(w2 + (size_t)e * DFF * DIM,
                   &g_W2t[(size_t)e * DIM * DFF], tile, n0, k0, DFF);
}

// ======== kernel 4: GEMM2 ========
__global__ __launch_bounds__(256, 2) void k_gemm2() {
    extern __shared__ char dynsmem[];
    gemm_body<DFF / 64, false>(blockIdx.z, dynsmem);
}

// ======== kernel 5: combine (fp16 O -> fp32 y) + counter reset for next run ==
__global__ void k_combine(float* __restrict__ y) {
    if (blockIdx.x == 0 && threadIdx.x < NEXP) {
        g_count[threadIdx.x] = 0;
        g_cursor[threadIdx.x] = 0;
    }
    int i = blockIdx.x * blockDim.x + threadIdx.x;   // over float4s of y
    const int V = DIM / 4;
    if (i >= N_TOK * V) return;
    int tok = i / V;
    int c   = i - tok * V;
    int p0 = g_tok2pair[2 * tok];
    int p1 = g_tok2pair[2 * tok + 1];
    const __half2* o0 = (const __half2*)(&g_O[0] + (size_t)p0 * DIM) + c * 2;
    const __half2* o1 = (const __half2*)(&g_O[0] + (size_t)p1 * DIM) + c * 2;
    float2 a0 = __half22float2(o0[0]);
    float2 a1 = __half22float2(o0[1]);
    float2 b0 = __half22float2(o1[0]);
    float2 b1 = __half22float2(o1[1]);
    float4 r;
    r.x = a0.x + b0.x; r.y = a0.y + b0.y;
    r.z = a1.x + b1.x; r.w = a1.y + b1.y;
    ((float4*)y)[i] = r;
}

// ======================= launch =======================
extern "C" void kernel_launch(void* const* d_in, const int* in_sizes, int n_in,
                              void* d_out, int out_size) {
    const float* x  = (const float*)d_in[0];   // [N, D]
    const float* gw = (const float*)d_in[1];   // [D, E]
    const float* w1 = (const float*)d_in[2];   // [E, D, DFF]
    const float* w2 = (const float*)d_in[3];   // [E, DFF, D]
    float* y = (float*)d_out;

    cudaFuncSetAttribute((const void*)k_gemm1_conv2,
                         cudaFuncAttributeMaxDynamicSharedMemorySize, SMEM_BYTES);
    cudaFuncSetAttribute((const void*)k_gemm2,
                         cudaFuncAttributeMaxDynamicSharedMemorySize, SMEM_BYTES);

    // #1: convert W1 + router (independent block ranges; counters cleaned by
    //     previous run's k_combine, or zero-initialized statics on first run)
    k_conv1_router<<<8192 + 256, 256>>>(w1, x, gw);
    // #2: assign
    k_assign<<<(N_TOK + 255) / 256, 256>>>();
    // #3: GEMM1 + convert W2 (piggybacked on spare z-slices)
    k_gemm1_conv2<<<dim3(DFF / 128, NPAIR / 128, NEXP + 2), 256, SMEM_BYTES>>>(w2);
    // #4: GEMM2  <-- ncu capture slot
    k_gemm2<<<dim3(DIM / 128, NPAIR / 128, NEXP), 256, SMEM_BYTES>>>();
    // #5: combine (+ counter reset for next graph replay)
    k_combine<<<(N_TOK * DIM / 4 + 255) / 256, 256>>>(y);
}